// round 11
// baseline (speedup 1.0000x reference)
#include <cuda_runtime.h>
#include <cuda_fp16.h>
#include <cstdint>

// ============================================================================
// GroupWiseLinearProjector, single-pass fp16 mma.sync GEMM (compute_103)
//   out[b,o,h,w] = sum_c x[b,c,h,w] * Wg[p(h,w),o,c],  p=(h%4)*4+(w%4)
// R11: x conversion fused INTO the GEMM. CTA = (b, r, otile, ht) owns all 4
//   q-phases -> per c it needs 4 contiguous 256B x rows: cp.async fp32
//   directly, convert in-kernel (LDS.128 -> half2 -> STS.32 into per-q SW64
//   tiles). convert_x pass and g_Xh scratch eliminated.
//   KC=32, 2-stage 160KB pipeline, R10 direct-store epilogue.
// ============================================================================

#define B_   16
#define CIN  512
#define COUT 512
#define KC   32          // 32 fp16 = 64B row, SW64 swizzle
#define NSTAGE 16        // 512 / 32

// ---------------- scratch (device globals; no allocation) ----------------
__device__ __align__(256) unsigned short g_Wh[16 * COUT * CIN];        // 8MB

// ---------------- helpers ----------------
__device__ __forceinline__ uint32_t smem_to_u32(const void* p) {
    uint32_t a;
    asm("{ .reg .u64 t; cvta.to.shared.u64 t, %1; cvt.u32.u64 %0, t; }"
        : "=r"(a) : "l"(p));
    return a;
}
__device__ __forceinline__ void cp_async16(uint32_t dst, const void* src) {
    asm volatile("cp.async.cg.shared.global [%0], [%1], 16;"
                 :: "r"(dst), "l"(src) : "memory");
}
#define CP_COMMIT() asm volatile("cp.async.commit_group;" ::: "memory")
#define CP_WAIT(n)  asm volatile("cp.async.wait_group %0;" :: "n"(n) : "memory")

__device__ __forceinline__ void ldmx4(uint32_t* r, uint32_t addr) {
    asm volatile("ldmatrix.sync.aligned.m8n8.x4.shared.b16 {%0,%1,%2,%3}, [%4];"
                 : "=r"(r[0]), "=r"(r[1]), "=r"(r[2]), "=r"(r[3]) : "r"(addr));
}
__device__ __forceinline__ void mma16816(float* d, const uint32_t* a,
                                         uint32_t b0, uint32_t b1) {
    asm volatile(
        "mma.sync.aligned.m16n8k16.row.col.f32.f16.f16.f32 "
        "{%0,%1,%2,%3}, {%4,%5,%6,%7}, {%8,%9}, {%0,%1,%2,%3};"
        : "+f"(d[0]), "+f"(d[1]), "+f"(d[2]), "+f"(d[3])
        : "r"(a[0]), "r"(a[1]), "r"(a[2]), "r"(a[3]), "r"(b0), "r"(b1));
}
// SW64 swizzle (64B rows, 8-row x 64B atom)
#define SWZ64(off) ((uint32_t)(off) ^ ((((uint32_t)(off)) >> 3) & 0x30))

// ============================================================================
// Pass 1: W -> fp16 (layout [ph][o][c])
// ============================================================================
__global__ __launch_bounds__(256)
void convert_w_kernel(const float* __restrict__ Wg) {
    size_t gt = (size_t)blockIdx.x * 256 + threadIdx.x;
    const float4* src = reinterpret_cast<const float4*>(Wg) + gt * 2;
    float4 a = src[0], b = src[1];
    float v[8] = {a.x, a.y, a.z, a.w, b.x, b.y, b.z, b.w};
    unsigned short hb[8];
#pragma unroll
    for (int i = 0; i < 8; i++)
        hb[i] = __half_as_ushort(__float2half_rn(v[i]));
    uint4 uh;
    uh.x = hb[0] | (uint32_t)hb[1] << 16;  uh.y = hb[2] | (uint32_t)hb[3] << 16;
    uh.z = hb[4] | (uint32_t)hb[5] << 16;  uh.w = hb[6] | (uint32_t)hb[7] << 16;
    *reinterpret_cast<uint4*>(g_Wh + gt * 8) = uh;
}

// ============================================================================
// Pass 2: fused convert + GEMM + unshuffle.
//   CTA = (b, r, otile 128o, ht): 4 sub-GEMMs (q), each 128o x 64px, K=512.
//   512 threads; warp = (q = wid&3, oq = wid>>2).
//   Stage (80KB): W 4qx8KB | Xq 4qx4KB | XS 32KB fp32 staging; x2 = 160KB.
// ============================================================================
#define STAGE_BYTES 81920
#define XQOFF 32768
#define XSOFF 49152

__global__ __launch_bounds__(512, 1)
void gwlp_mma_kernel(const float* __restrict__ x, float* __restrict__ out) {
    extern __shared__ __align__(1024) char sm[];
    const uint32_t smb = smem_to_u32(sm);

    const int t   = threadIdx.x;
    const int wid = t >> 5;
    const int lid = t & 31;
    const int q   = wid & 3;    // phase column of this warp
    const int oq  = wid >> 2;   // o quarter (32 rows)

    const int bid   = blockIdx.x;   // 1024: ht fastest (share W in L2)
    const int ht    = bid & 3;
    const int otile = (bid >> 2) & 3;
    const int r     = (bid >> 4) & 3;
    const int b     = bid >> 6;
    const int o0    = otile * 128;

    const unsigned short* whp0 = g_Wh + ((size_t)(r * 4) * COUT + o0) * CIN;
    // x rows this CTA needs: h = 16*ht + 4*h4l + r, full 64-wide w lines
    const float* xbase = x + (((size_t)b * CIN) * 64 + (size_t)(16 * ht + r)) * 64;

    // ---- stage loader: 8 x 16B cp.async per thread ----
    auto load_stage = [&](int s, int buf) {
        const uint32_t sb = smb + (uint32_t)buf * STAGE_BYTES;
        const int ce = s * KC;
        // W fp16: 4q x 128 rows x 4 granules = 2048
#pragma unroll
        for (int i = 0; i < 4; i++) {
            int gi  = t + i * 512;
            int lq  = gi >> 9;
            int wi  = gi & 511;
            int row = wi >> 2, g = wi & 3;
            uint32_t d = sb + lq * 8192 + SWZ64(row * 64 + g * 16);
            cp_async16(d, whp0 + (size_t)lq * (COUT * CIN) + (size_t)row * CIN + ce + g * 8);
        }
        // XS fp32: 32c x 4h x 16 granules = 2048  (rows of 256B, no swizzle)
#pragma unroll
        for (int i = 0; i < 4; i++) {
            int gi  = t + i * 512;
            int c   = gi >> 6;
            int rem = gi & 63;
            int h4l = rem >> 4, g = rem & 15;
            uint32_t d = sb + XSOFF + (uint32_t)((c * 4 + h4l) * 256 + g * 16);
            cp_async16(d, xbase + (size_t)(ce + c) * 4096 + h4l * 256 + g * 4);
        }
        CP_COMMIT();
    };

    // ---- convert: XS fp32 -> 4 q-tiles fp16 (SW64) ----
    // thread: w4 = t&15, h4l = (t>>4)&3, c8 = t>>6 (c group of 4)
    auto convert_stage = [&](int buf) {
        const uint32_t sb = smb + (uint32_t)buf * STAGE_BYTES;
        const float4* XS4 = reinterpret_cast<const float4*>(sm + (size_t)buf * STAGE_BYTES + XSOFF);
        const int w4  = t & 15;
        const int h4l = (t >> 4) & 3;
        const int c8  = t >> 6;
        const int px  = h4l * 16 + w4;
#pragma unroll
        for (int cc = 0; cc < 2; cc++) {
            int c0 = c8 * 4 + cc * 2;
            float4 f0 = XS4[(c0 * 4 + h4l) * 16 + w4];
            float4 f1 = XS4[((c0 + 1) * 4 + h4l) * 16 + w4];
            float v0[4] = {f0.x, f0.y, f0.z, f0.w};   // q = w % 4
            float v1[4] = {f1.x, f1.y, f1.z, f1.w};
#pragma unroll
            for (int lq = 0; lq < 4; lq++) {
                __half2 hv = __floats2half2_rn(v0[lq], v1[lq]);
                uint32_t d = sb + XQOFF + lq * 4096 + SWZ64(px * 64 + c0 * 2);
                asm volatile("st.shared.b32 [%0], %1;"
                             :: "r"(d), "r"(*reinterpret_cast<uint32_t*>(&hv)) : "memory");
            }
        }
    };

    // ---- per-lane ldmatrix address components (SW64 keys) ----
    const int lr = lid & 15;
    const int cb = lid >> 4;
    const uint32_t wq_off = (uint32_t)q * 8192;
    const uint32_t xq_off = XQOFF + (uint32_t)q * 4096;
    uint32_t a_off[2], a_key[2];
#pragma unroll
    for (int mt = 0; mt < 2; mt++) {
        int row = oq * 32 + mt * 16 + lr;
        a_off[mt] = (uint32_t)row * 64;
        a_key[mt] = (uint32_t)((row >> 1) & 3) << 4;
    }
    uint32_t b_off[4], b_key[4];
#pragma unroll
    for (int j = 0; j < 4; j++) {
        int row = j * 16 + lr;              // px rows 0..63
        b_off[j] = (uint32_t)row * 64;
        b_key[j] = (uint32_t)((row >> 1) & 3) << 4;
    }

    float acc[2][8][4];
#pragma unroll
    for (int mt = 0; mt < 2; mt++)
#pragma unroll
        for (int nt = 0; nt < 8; nt++)
#pragma unroll
            for (int e = 0; e < 4; e++)
                acc[mt][nt][e] = 0.0f;

    // ---- 2-stage pipeline: wait -> convert -> mma -> load(ck+2) ----
    load_stage(0, 0);
    load_stage(1, 1);

#pragma unroll 1
    for (int ck = 0; ck < NSTAGE; ck++) {
        if (ck == NSTAGE - 1) { CP_WAIT(0); } else { CP_WAIT(1); }
        __syncthreads();
        convert_stage(ck & 1);
        __syncthreads();

        const uint32_t sb = smb + (uint32_t)(ck & 1) * STAGE_BYTES;
#pragma unroll
        for (int ks = 0; ks < 2; ks++) {
            const uint32_t col = (uint32_t)(ks * 32 + cb * 16);
            uint32_t bh[4][4];
#pragma unroll
            for (int j = 0; j < 4; j++)
                ldmx4(bh[j], sb + xq_off + b_off[j] + (col ^ b_key[j]));
#pragma unroll
            for (int mt = 0; mt < 2; mt++) {
                uint32_t ah[4];
                ldmx4(ah, sb + wq_off + a_off[mt] + (col ^ a_key[mt]));
#pragma unroll
                for (int j = 0; j < 4; j++) {
                    mma16816(acc[mt][2 * j],     ah, bh[j][0], bh[j][2]);
                    mma16816(acc[mt][2 * j + 1], ah, bh[j][1], bh[j][3]);
                }
            }
        }
        __syncthreads();
        if (ck + 2 < NSTAGE) load_stage(ck + 2, ck & 1);
    }

    // ---- fused epilogue: acc -> smem rows -> coalesced out stores ----
    float* S = reinterpret_cast<float*>(sm);   // 512 rows x 68 floats = 136KB
    {
        const int g  = lid >> 2;
        const int tq = lid & 3;
#pragma unroll
        for (int mt = 0; mt < 2; mt++) {
#pragma unroll
            for (int nt = 0; nt < 8; nt++) {
                int px  = nt * 8 + tq * 2;      // local px (0..63)
                int h4l = px >> 4;
                int w4  = px & 15;
                int w0  = 4 * w4 + q;
                int o_lo = oq * 32 + mt * 16 + g;
                int R0 = (o_lo)     * 4 + h4l;
                int R1 = (o_lo + 8) * 4 + h4l;
                S[R0 * 68 + w0]     = acc[mt][nt][0];
                S[R0 * 68 + w0 + 4] = acc[mt][nt][1];
                S[R1 * 68 + w0]     = acc[mt][nt][2];
                S[R1 * 68 + w0 + 4] = acc[mt][nt][3];
            }
        }
    }
    __syncthreads();

    // stores: 512 rows x 64 floats; half-warps cover full 256B rows.
    {
        const int f4  = t & 15;
        const int rl0 = t >> 4;                 // 0..31
#pragma unroll
        for (int p = 0; p < 16; p++) {
            int rowid = p * 32 + rl0;           // 0..511
            int o    = rowid >> 2;
            int h4l  = rowid & 3;
            int h    = 16 * ht + 4 * h4l + r;
            float4 v = *reinterpret_cast<const float4*>(&S[rowid * 68 + f4 * 4]);
            float* dst = out + (((size_t)b * COUT + o0 + o) * 64 + h) * 64 + f4 * 4;
            *reinterpret_cast<float4*>(dst) = v;
        }
    }
}

// ============================================================================
extern "C" void kernel_launch(void* const* d_in, const int* in_sizes, int n_in,
                              void* d_out, int out_size)
{
    const float* x  = (const float*)d_in[0];   // [16, 512, 64, 64]
    const float* Wg = (const float*)d_in[1];   // [16, 512, 512]
    float* out = (float*)d_out;                // [16, 512, 64, 64]

    cudaFuncSetAttribute(gwlp_mma_kernel,
                         cudaFuncAttributeMaxDynamicSharedMemorySize, 2 * STAGE_BYTES);

    convert_w_kernel<<<2048, 256>>>(Wg);
    gwlp_mma_kernel<<<1024, 512, 2 * STAGE_BYTES>>>(x, out);
}

// round 12
// speedup vs baseline: 1.1258x; 1.1258x over previous
#include <cuda_runtime.h>
#include <cuda_fp16.h>
#include <cstdint>

// ============================================================================
// GroupWiseLinearProjector, single-pass fp16 mma.sync GEMM (compute_103)
//   out[b,o,h,w] = sum_c x[b,c,h,w] * Wg[p(h,w),o,c],  p=(h%4)*4+(w%4)
// R12: R10 structure (separate converts, 4-q CTA, direct-store epilogue)
//   with HALF-SIZE CTAs (64o x 4x64px, 256 thr, 96KB) so 2 CTAs/SM:
//   CTA B's mainloop overlaps CTA A's prologue + epilogue.
//   KC=32/SW64, 3-stage pipeline.
// ============================================================================

#define B_   16
#define CIN  512
#define COUT 512
#define NPX  256
#define KC   32          // 32 fp16 = 64B row, SW64 swizzle
#define NSTAGE 16        // 512 / 32

// ---------------- scratch (device globals; no allocation) ----------------
__device__ __align__(256) unsigned short g_Xh[B_ * 16 * NPX * CIN];    // 64MB
__device__ __align__(256) unsigned short g_Wh[16 * COUT * CIN];        // 8MB

// ---------------- helpers ----------------
__device__ __forceinline__ uint32_t smem_to_u32(const void* p) {
    uint32_t a;
    asm("{ .reg .u64 t; cvta.to.shared.u64 t, %1; cvt.u32.u64 %0, t; }"
        : "=r"(a) : "l"(p));
    return a;
}
__device__ __forceinline__ void cp_async16(uint32_t dst, const void* src) {
    asm volatile("cp.async.cg.shared.global [%0], [%1], 16;"
                 :: "r"(dst), "l"(src) : "memory");
}
#define CP_COMMIT() asm volatile("cp.async.commit_group;" ::: "memory")
#define CP_WAIT(n)  asm volatile("cp.async.wait_group %0;" :: "n"(n) : "memory")

__device__ __forceinline__ void ldmx4(uint32_t* r, uint32_t addr) {
    asm volatile("ldmatrix.sync.aligned.m8n8.x4.shared.b16 {%0,%1,%2,%3}, [%4];"
                 : "=r"(r[0]), "=r"(r[1]), "=r"(r[2]), "=r"(r[3]) : "r"(addr));
}
__device__ __forceinline__ void mma16816(float* d, const uint32_t* a,
                                         uint32_t b0, uint32_t b1) {
    asm volatile(
        "mma.sync.aligned.m16n8k16.row.col.f32.f16.f16.f32 "
        "{%0,%1,%2,%3}, {%4,%5,%6,%7}, {%8,%9}, {%0,%1,%2,%3};"
        : "+f"(d[0]), "+f"(d[1]), "+f"(d[2]), "+f"(d[3])
        : "r"(a[0]), "r"(a[1]), "r"(a[2]), "r"(a[3]), "r"(b0), "r"(b1));
}
// SW64 swizzle (64B rows, 8-row x 64B atom); ldmatrix key = ((row>>1)&3)<<4
#define SWZ64(off) ((uint32_t)(off) ^ ((((uint32_t)(off)) >> 3) & 0x30))

// ============================================================================
// Pass 1a: W -> fp16 (layout [ph][o][c])
// ============================================================================
__global__ __launch_bounds__(256)
void convert_w_kernel(const float* __restrict__ Wg) {
    size_t gt = (size_t)blockIdx.x * 256 + threadIdx.x;
    const float4* src = reinterpret_cast<const float4*>(Wg) + gt * 2;
    float4 a = src[0], b = src[1];
    float v[8] = {a.x, a.y, a.z, a.w, b.x, b.y, b.z, b.w};
    unsigned short hb[8];
#pragma unroll
    for (int i = 0; i < 8; i++)
        hb[i] = __half_as_ushort(__float2half_rn(v[i]));
    uint4 uh;
    uh.x = hb[0] | (uint32_t)hb[1] << 16;  uh.y = hb[2] | (uint32_t)hb[3] << 16;
    uh.z = hb[4] | (uint32_t)hb[5] << 16;  uh.w = hb[6] | (uint32_t)hb[7] << 16;
    *reinterpret_cast<uint4*>(g_Wh + gt * 8) = uh;
}

// ============================================================================
// Pass 1b: x -> fp16 in [b][phase][px][c] (K-major)
// ============================================================================
__global__ __launch_bounds__(256)
void convert_x_kernel(const float* __restrict__ x) {
    __shared__ float sin[64][68];
    int bid = blockIdx.x;                 // 16 * 64 * 8 = 8192
    int cc = bid & 7;
    int h  = (bid >> 3) & 63;
    int b  = bid >> 9;
    int c0 = cc * 64;
    int t  = threadIdx.x;

    const float* src = x + (((size_t)b * CIN + c0) * 64 + h) * 64;
    {
        int c  = t >> 2;
        int f0 = t & 3;
#pragma unroll
        for (int j = 0; j < 4; j++) {
            float4 v = *reinterpret_cast<const float4*>(src + (size_t)c * 4096 + (f0 + 4 * j) * 4);
            *reinterpret_cast<float4*>(&sin[c][(f0 + 4 * j) * 4]) = v;
        }
    }
    __syncthreads();

    int p   = t >> 2;
    int q   = p >> 4;
    int w4  = p & 15;
    int cc4 = t & 3;
    int r   = h & 3;
    int h4  = h >> 2;

    unsigned short hb[16];
#pragma unroll
    for (int i = 0; i < 16; i++)
        hb[i] = __half_as_ushort(__float2half_rn(sin[cc4 * 16 + i][q + 4 * w4]));

    int phase = r * 4 + q;
    int px    = h4 * 16 + w4;
    size_t off = (((size_t)(b * 16 + phase) * NPX) + px) * CIN + c0 + cc4 * 16;

    uint4 u0, u1;
    u0.x = hb[0] | (uint32_t)hb[1] << 16;   u0.y = hb[2]  | (uint32_t)hb[3] << 16;
    u0.z = hb[4] | (uint32_t)hb[5] << 16;   u0.w = hb[6]  | (uint32_t)hb[7] << 16;
    u1.x = hb[8] | (uint32_t)hb[9] << 16;   u1.y = hb[10] | (uint32_t)hb[11] << 16;
    u1.z = hb[12]| (uint32_t)hb[13] << 16;  u1.w = hb[14] | (uint32_t)hb[15] << 16;
    *reinterpret_cast<uint4*>(g_Xh + off)     = u0;
    *reinterpret_cast<uint4*>(g_Xh + off + 8) = u1;
}

// ============================================================================
// Pass 2: fused GEMM+unshuffle, 2 CTAs/SM.
//   CTA = (b, r, otile 64o, ht): 4 sub-GEMMs (q), each 64o x 64px, K=512.
//   256 threads; warp = (q = wid&3, oq = wid>>2); warp tile 32o x 64px.
//   Stage (32KB): W 4qx4KB | X 4qx4KB; 3 stages = 96KB.
//   Epilogue: acc -> 70KB smem rows -> coalesced STG.128 to out.
// ============================================================================
#define STAGE_BYTES 32768
#define XOFF 16384

__global__ __launch_bounds__(256, 2)
void gwlp_mma_kernel(float* __restrict__ out) {
    extern __shared__ __align__(1024) char sm[];
    const uint32_t smb = smem_to_u32(sm);

    const int t   = threadIdx.x;
    const int wid = t >> 5;
    const int lid = t & 31;
    const int q   = wid & 3;    // phase column of this warp
    const int oq  = wid >> 2;   // o half (32 rows)

    const int bid   = blockIdx.x;   // 2048: ht fastest (share W in L2)
    const int ht    = bid & 3;
    const int otile = (bid >> 2) & 7;
    const int r     = (bid >> 5) & 3;
    const int b     = bid >> 7;
    const int o0    = otile * 64;
    const int px0   = ht * 64;

    const unsigned short* whp0 = g_Wh + ((size_t)(r * 4) * COUT + o0) * CIN;
    const unsigned short* xhp0 = g_Xh + ((size_t)(b * 16 + r * 4) * NPX + px0) * CIN;

    // ---- stage loader: 8 x 16B cp.async per thread ----
    auto load_stage = [&](int s, int buf) {
        const uint32_t sb = smb + (uint32_t)buf * STAGE_BYTES;
        const int ce = s * KC;
        // W: 4q x 64 rows x 4 granules = 1024
#pragma unroll
        for (int i = 0; i < 4; i++) {
            int gi  = t + i * 256;
            int lq  = gi >> 8;
            int wi  = gi & 255;
            int row = wi >> 2, g = wi & 3;
            uint32_t d = sb + lq * 4096 + SWZ64(row * 64 + g * 16);
            cp_async16(d, whp0 + (size_t)lq * (COUT * CIN) + (size_t)row * CIN + ce + g * 8);
        }
        // X: 4q x 64 rows x 4 granules = 1024
#pragma unroll
        for (int i = 0; i < 4; i++) {
            int gi  = t + i * 256;
            int lq  = gi >> 8;
            int wi  = gi & 255;
            int row = wi >> 2, g = wi & 3;
            uint32_t d = sb + XOFF + lq * 4096 + SWZ64(row * 64 + g * 16);
            cp_async16(d, xhp0 + (size_t)lq * (NPX * CIN) + (size_t)row * CIN + ce + g * 8);
        }
        CP_COMMIT();
    };

    // ---- per-lane ldmatrix address components (SW64 keys) ----
    const int lr = lid & 15;
    const int cb = lid >> 4;
    const uint32_t wq_off = (uint32_t)q * 4096;
    const uint32_t xq_off = XOFF + (uint32_t)q * 4096;
    uint32_t a_off[2], a_key[2];
#pragma unroll
    for (int mt = 0; mt < 2; mt++) {
        int row = oq * 32 + mt * 16 + lr;
        a_off[mt] = (uint32_t)row * 64;
        a_key[mt] = (uint32_t)((row >> 1) & 3) << 4;
    }
    uint32_t b_off[4], b_key[4];
#pragma unroll
    for (int j = 0; j < 4; j++) {
        int row = j * 16 + lr;              // px rows 0..63
        b_off[j] = (uint32_t)row * 64;
        b_key[j] = (uint32_t)((row >> 1) & 3) << 4;
    }

    float acc[2][8][4];
#pragma unroll
    for (int mt = 0; mt < 2; mt++)
#pragma unroll
        for (int nt = 0; nt < 8; nt++)
#pragma unroll
            for (int e = 0; e < 4; e++)
                acc[mt][nt][e] = 0.0f;

    // ---- 3-stage pipeline, single sync per stage ----
    load_stage(0, 0);
    load_stage(1, 1);

#pragma unroll 1
    for (int ck = 0; ck < NSTAGE; ck++) {
        if (ck == NSTAGE - 1) { CP_WAIT(0); } else { CP_WAIT(1); }
        __syncthreads();
        // buffer (ck+2)%3 == (ck-1)%3: computed last iter, safe after sync.
        {
            int nb = ck + 2;
            if (nb < NSTAGE) load_stage(nb, nb % 3);
        }

        const uint32_t sb = smb + (uint32_t)(ck % 3) * STAGE_BYTES;
#pragma unroll
        for (int ks = 0; ks < 2; ks++) {
            const uint32_t col = (uint32_t)(ks * 32 + cb * 16);
            uint32_t bh[4][4];
#pragma unroll
            for (int j = 0; j < 4; j++)
                ldmx4(bh[j], sb + xq_off + b_off[j] + (col ^ b_key[j]));
#pragma unroll
            for (int mt = 0; mt < 2; mt++) {
                uint32_t ah[4];
                ldmx4(ah, sb + wq_off + a_off[mt] + (col ^ a_key[mt]));
#pragma unroll
                for (int j = 0; j < 4; j++) {
                    mma16816(acc[mt][2 * j],     ah, bh[j][0], bh[j][2]);
                    mma16816(acc[mt][2 * j + 1], ah, bh[j][1], bh[j][3]);
                }
            }
        }
    }

    // ---- fused epilogue: acc -> smem rows -> coalesced out stores ----
    // S: 256 rows (o_local*4 + h4l) x 68 floats = 69632 B
    __syncthreads();
    float* S = reinterpret_cast<float*>(sm);
    {
        const int g  = lid >> 2;
        const int tq = lid & 3;
#pragma unroll
        for (int mt = 0; mt < 2; mt++) {
#pragma unroll
            for (int nt = 0; nt < 8; nt++) {
                int px  = nt * 8 + tq * 2;      // local px (0..63)
                int h4l = px >> 4;
                int w4  = px & 15;
                int w0  = 4 * w4 + q;
                int o_lo = oq * 32 + mt * 16 + g;
                int R0 = (o_lo)     * 4 + h4l;
                int R1 = (o_lo + 8) * 4 + h4l;
                S[R0 * 68 + w0]     = acc[mt][nt][0];
                S[R0 * 68 + w0 + 4] = acc[mt][nt][1];
                S[R1 * 68 + w0]     = acc[mt][nt][2];
                S[R1 * 68 + w0 + 4] = acc[mt][nt][3];
            }
        }
    }
    __syncthreads();

    // stores: 256 rows x 64 floats; half-warps cover full 256B rows.
    {
        const int f4  = t & 15;
        const int rl0 = t >> 4;                 // 0..15
#pragma unroll
        for (int p = 0; p < 16; p++) {
            int rowid = p * 16 + rl0;           // 0..255
            int o    = rowid >> 2;
            int h4l  = rowid & 3;
            int h    = 16 * ht + 4 * h4l + r;
            float4 v = *reinterpret_cast<const float4*>(&S[rowid * 68 + f4 * 4]);
            float* dst = out + (((size_t)b * COUT + o0 + o) * 64 + h) * 64 + f4 * 4;
            *reinterpret_cast<float4*>(dst) = v;
        }
    }
}

// ============================================================================
extern "C" void kernel_launch(void* const* d_in, const int* in_sizes, int n_in,
                              void* d_out, int out_size)
{
    const float* x  = (const float*)d_in[0];   // [16, 512, 64, 64]
    const float* Wg = (const float*)d_in[1];   // [16, 512, 512]
    float* out = (float*)d_out;                // [16, 512, 64, 64]

    cudaFuncSetAttribute(gwlp_mma_kernel,
                         cudaFuncAttributeMaxDynamicSharedMemorySize, 3 * STAGE_BYTES);

    convert_w_kernel<<<2048, 256>>>(Wg);
    convert_x_kernel<<<8192, 256>>>(x);
    gwlp_mma_kernel<<<2048, 256, 3 * STAGE_BYTES>>>(out);
}

// round 13
// speedup vs baseline: 1.3431x; 1.1931x over previous
#include <cuda_runtime.h>
#include <cuda_fp16.h>
#include <cstdint>

// ============================================================================
// GroupWiseLinearProjector, single-pass fp16 mma.sync GEMM (compute_103)
//   out[b,o,h,w] = sum_c x[b,c,h,w] * Wg[p(h,w),o,c],  p=(h%4)*4+(w%4)
// R13: R10 base + conflict-fixed epilogue staging (S[R*77 + q*19 + w4],
//   8-way -> 2-way STS banks) + converts merged into one launch.
// ============================================================================

#define B_   16
#define CIN  512
#define COUT 512
#define NPX  256
#define KC   64          // K chunk (64 fp16 = 128B row, SW128 swizzle)
#define NSTAGE 8         // 512 / 64

// ---------------- scratch (device globals; no allocation) ----------------
__device__ __align__(256) unsigned short g_Xh[B_ * 16 * NPX * CIN];    // 64MB
__device__ __align__(256) unsigned short g_Wh[16 * COUT * CIN];        // 8MB

// ---------------- helpers ----------------
__device__ __forceinline__ uint32_t smem_to_u32(const void* p) {
    uint32_t a;
    asm("{ .reg .u64 t; cvta.to.shared.u64 t, %1; cvt.u32.u64 %0, t; }"
        : "=r"(a) : "l"(p));
    return a;
}
__device__ __forceinline__ void cp_async16(uint32_t dst, const void* src) {
    asm volatile("cp.async.cg.shared.global [%0], [%1], 16;"
                 :: "r"(dst), "l"(src) : "memory");
}
#define CP_COMMIT() asm volatile("cp.async.commit_group;" ::: "memory")
#define CP_WAIT(n)  asm volatile("cp.async.wait_group %0;" :: "n"(n) : "memory")

__device__ __forceinline__ void ldmx4(uint32_t* r, uint32_t addr) {
    asm volatile("ldmatrix.sync.aligned.m8n8.x4.shared.b16 {%0,%1,%2,%3}, [%4];"
                 : "=r"(r[0]), "=r"(r[1]), "=r"(r[2]), "=r"(r[3]) : "r"(addr));
}
__device__ __forceinline__ void mma16816(float* d, const uint32_t* a,
                                         uint32_t b0, uint32_t b1) {
    asm volatile(
        "mma.sync.aligned.m16n8k16.row.col.f32.f16.f16.f32 "
        "{%0,%1,%2,%3}, {%4,%5,%6,%7}, {%8,%9}, {%0,%1,%2,%3};"
        : "+f"(d[0]), "+f"(d[1]), "+f"(d[2]), "+f"(d[3])
        : "r"(a[0]), "r"(a[1]), "r"(a[2]), "r"(a[3]), "r"(b0), "r"(b1));
}
#define SWZ(off) ((uint32_t)(off) ^ ((((uint32_t)(off)) >> 3) & 0x70))

// ============================================================================
// Pass 1 (merged): blocks [0,2048) convert W; [2048,10240) convert x.
// ============================================================================
__global__ __launch_bounds__(256)
void convert_kernel(const float* __restrict__ Wg, const float* __restrict__ x) {
    if (blockIdx.x < 2048) {
        // ---- W -> fp16, layout [ph][o][c] ----
        size_t gt = (size_t)blockIdx.x * 256 + threadIdx.x;
        const float4* src = reinterpret_cast<const float4*>(Wg) + gt * 2;
        float4 a = src[0], b = src[1];
        float v[8] = {a.x, a.y, a.z, a.w, b.x, b.y, b.z, b.w};
        unsigned short hb[8];
#pragma unroll
        for (int i = 0; i < 8; i++)
            hb[i] = __half_as_ushort(__float2half_rn(v[i]));
        uint4 uh;
        uh.x = hb[0] | (uint32_t)hb[1] << 16;  uh.y = hb[2] | (uint32_t)hb[3] << 16;
        uh.z = hb[4] | (uint32_t)hb[5] << 16;  uh.w = hb[6] | (uint32_t)hb[7] << 16;
        *reinterpret_cast<uint4*>(g_Wh + gt * 8) = uh;
        return;
    }
    // ---- x -> fp16 in [b][phase][px][c] (K-major) ----
    __shared__ float sin[64][68];
    int bid = blockIdx.x - 2048;          // 16 * 64 * 8 = 8192
    int cc = bid & 7;
    int h  = (bid >> 3) & 63;
    int b  = bid >> 9;
    int c0 = cc * 64;
    int t  = threadIdx.x;

    const float* src = x + (((size_t)b * CIN + c0) * 64 + h) * 64;
    {
        int c  = t >> 2;
        int f0 = t & 3;
#pragma unroll
        for (int j = 0; j < 4; j++) {
            float4 v = *reinterpret_cast<const float4*>(src + (size_t)c * 4096 + (f0 + 4 * j) * 4);
            *reinterpret_cast<float4*>(&sin[c][(f0 + 4 * j) * 4]) = v;
        }
    }
    __syncthreads();

    int p   = t >> 2;
    int q   = p >> 4;
    int w4  = p & 15;
    int cc4 = t & 3;
    int r   = h & 3;
    int h4  = h >> 2;

    unsigned short hb[16];
#pragma unroll
    for (int i = 0; i < 16; i++)
        hb[i] = __half_as_ushort(__float2half_rn(sin[cc4 * 16 + i][q + 4 * w4]));

    int phase = r * 4 + q;
    int px    = h4 * 16 + w4;
    size_t off = (((size_t)(b * 16 + phase) * NPX) + px) * CIN + c0 + cc4 * 16;

    uint4 u0, u1;
    u0.x = hb[0] | (uint32_t)hb[1] << 16;   u0.y = hb[2]  | (uint32_t)hb[3] << 16;
    u0.z = hb[4] | (uint32_t)hb[5] << 16;   u0.w = hb[6]  | (uint32_t)hb[7] << 16;
    u1.x = hb[8] | (uint32_t)hb[9] << 16;   u1.y = hb[10] | (uint32_t)hb[11] << 16;
    u1.z = hb[12]| (uint32_t)hb[13] << 16;  u1.w = hb[14] | (uint32_t)hb[15] << 16;
    *reinterpret_cast<uint4*>(g_Xh + off)     = u0;
    *reinterpret_cast<uint4*>(g_Xh + off + 8) = u1;
}

// ============================================================================
// Pass 2: fused GEMM+unshuffle (R10 structure).
//   CTA = (b, r, otile 128o, ht): 4 sub-GEMMs (q), each 128o x 64px, K=512.
//   512 threads; warp = (q = wid&3, oq = wid>>2).
//   Stage (96KB): W[q] 4x16KB | X[q] 4x8KB; double-buffered = 192KB.
//   Epilogue: S[R*77 + q*19 + w4]  (2-way max banks) -> coalesced STG.128.
// ============================================================================
#define STAGE_BYTES 98304
#define XOFF 65536

__global__ __launch_bounds__(512, 1)
void gwlp_mma_kernel(float* __restrict__ out) {
    extern __shared__ __align__(1024) char sm[];
    const uint32_t smb = smem_to_u32(sm);

    const int t   = threadIdx.x;
    const int wid = t >> 5;
    const int lid = t & 31;
    const int q   = wid & 3;    // phase column of this warp
    const int oq  = wid >> 2;   // o quarter (32 rows)

    const int bid   = blockIdx.x;   // 1024: ht fastest (share W,X in L2)
    const int ht    = bid & 3;
    const int otile = (bid >> 2) & 3;
    const int r     = (bid >> 4) & 3;
    const int b     = bid >> 6;
    const int o0    = otile * 128;
    const int px0   = ht * 64;

    const unsigned short* whp0 = g_Wh + ((size_t)(r * 4) * COUT + o0) * CIN;
    const unsigned short* xhp0 = g_Xh + ((size_t)(b * 16 + r * 4) * NPX + px0) * CIN;

    // ---- stage loader: 12 x 16B cp.async per thread ----
    auto load_stage = [&](int s, int buf) {
        const uint32_t sb = smb + (uint32_t)buf * STAGE_BYTES;
        const int ce = s * KC;
#pragma unroll
        for (int i = 0; i < 8; i++) {      // W: 4096 granules (4q x 128 x 8)
            int gi  = t + i * 512;
            int lq  = gi >> 10;
            int wi  = gi & 1023;
            int row = wi >> 3, g = wi & 7;
            uint32_t d = sb + lq * 16384 + SWZ(row * 128 + g * 16);
            cp_async16(d, whp0 + (size_t)lq * (COUT * CIN) + (size_t)row * CIN + ce + g * 8);
        }
#pragma unroll
        for (int i = 0; i < 4; i++) {      // X: 2048 granules (4q x 64 x 8)
            int gi  = t + i * 512;
            int lq  = gi >> 9;
            int wi  = gi & 511;
            int row = wi >> 3, g = wi & 7;
            uint32_t d = sb + XOFF + lq * 8192 + SWZ(row * 128 + g * 16);
            cp_async16(d, xhp0 + (size_t)lq * (NPX * CIN) + (size_t)row * CIN + ce + g * 8);
        }
        CP_COMMIT();
    };

    // ---- per-lane ldmatrix address components ----
    const int lr = lid & 15;
    const int cb = lid >> 4;
    const uint32_t wq_off = (uint32_t)q * 16384;
    const uint32_t xq_off = XOFF + (uint32_t)q * 8192;
    uint32_t a_off[2], a_key[2];
#pragma unroll
    for (int mt = 0; mt < 2; mt++) {
        int row = oq * 32 + mt * 16 + lr;
        a_off[mt] = (uint32_t)row * 128;
        a_key[mt] = (uint32_t)(row & 7) << 4;
    }
    uint32_t b_off[4], b_key[4];
#pragma unroll
    for (int j = 0; j < 4; j++) {
        int row = j * 16 + lr;              // px rows 0..63
        b_off[j] = (uint32_t)row * 128;
        b_key[j] = (uint32_t)(row & 7) << 4;
    }

    float acc[2][8][4];
#pragma unroll
    for (int mt = 0; mt < 2; mt++)
#pragma unroll
        for (int nt = 0; nt < 8; nt++)
#pragma unroll
            for (int e = 0; e < 4; e++)
                acc[mt][nt][e] = 0.0f;

    // ---- 2-stage pipeline ----
    load_stage(0, 0);
    load_stage(1, 1);

#pragma unroll 1
    for (int ck = 0; ck < NSTAGE; ck++) {
        if (ck == NSTAGE - 1) { CP_WAIT(0); } else { CP_WAIT(1); }
        __syncthreads();

        const uint32_t sb = smb + (uint32_t)(ck & 1) * STAGE_BYTES;
#pragma unroll
        for (int ks = 0; ks < 4; ks++) {
            const uint32_t col = (uint32_t)(ks * 32 + cb * 16);
            uint32_t bh[4][4];
#pragma unroll
            for (int j = 0; j < 4; j++)
                ldmx4(bh[j], sb + xq_off + b_off[j] + (col ^ b_key[j]));
#pragma unroll
            for (int mt = 0; mt < 2; mt++) {
                uint32_t ah[4];
                ldmx4(ah, sb + wq_off + a_off[mt] + (col ^ a_key[mt]));
#pragma unroll
                for (int j = 0; j < 4; j++) {
                    mma16816(acc[mt][2 * j],     ah, bh[j][0], bh[j][2]);
                    mma16816(acc[mt][2 * j + 1], ah, bh[j][1], bh[j][3]);
                }
            }
        }
        __syncthreads();
        if (ck + 2 < NSTAGE) load_stage(ck + 2, ck & 1);
    }

    // ---- fused epilogue: acc -> S[R*77 + q*19 + w4] -> coalesced stores ----
    // S: 512 rows x 77 floats = 157,696 B (< 192KB smem already allocated)
    __syncthreads();
    float* S = reinterpret_cast<float*>(sm);
    {
        const int g  = lid >> 2;
        const int tq = lid & 3;
#pragma unroll
        for (int mt = 0; mt < 2; mt++) {
#pragma unroll
            for (int nt = 0; nt < 8; nt++) {
                int px   = nt * 8 + tq * 2;     // even, so px+1 shares h4l
                int h4l  = px >> 4;
                int w4a  = px & 15;
                int o_lo = oq * 32 + mt * 16 + g;
                int R0 = (o_lo)     * 4 + h4l;
                int R1 = (o_lo + 8) * 4 + h4l;
                int base0 = R0 * 77 + q * 19 + w4a;
                int base1 = R1 * 77 + q * 19 + w4a;
                S[base0]     = acc[mt][nt][0];
                S[base0 + 1] = acc[mt][nt][1];
                S[base1]     = acc[mt][nt][2];
                S[base1 + 1] = acc[mt][nt][3];
            }
        }
    }
    __syncthreads();

    // stores: 512 rows x 64 floats; gather q=0..3 per w4 block, STG.128.
    {
        const int f4  = t & 15;
        const int rl0 = t >> 4;                 // 0..31
#pragma unroll
        for (int p = 0; p < 16; p++) {
            int rowid = p * 32 + rl0;           // 0..511
            int o    = rowid >> 2;
            int h4l  = rowid & 3;
            int h    = 16 * ht + 4 * h4l + r;
            int sb0  = rowid * 77 + f4;
            float4 v;
            v.x = S[sb0];
            v.y = S[sb0 + 19];
            v.z = S[sb0 + 38];
            v.w = S[sb0 + 57];
            float* dst = out + (((size_t)b * COUT + o0 + o) * 64 + h) * 64 + f4 * 4;
            *reinterpret_cast<float4*>(dst) = v;
        }
    }
}

// ============================================================================
extern "C" void kernel_launch(void* const* d_in, const int* in_sizes, int n_in,
                              void* d_out, int out_size)
{
    const float* x  = (const float*)d_in[0];   // [16, 512, 64, 64]
    const float* Wg = (const float*)d_in[1];   // [16, 512, 512]
    float* out = (float*)d_out;                // [16, 512, 64, 64]

    cudaFuncSetAttribute(gwlp_mma_kernel,
                         cudaFuncAttributeMaxDynamicSharedMemorySize, 2 * STAGE_BYTES);

    convert_kernel<<<10240, 256>>>(Wg, x);
    gwlp_mma_kernel<<<1024, 512, 2 * STAGE_BYTES>>>(out);
}